// round 16
// baseline (speedup 1.0000x reference)
#include <cuda_runtime.h>
#include <cuda_fp16.h>
#include <mma.h>
#include <cstdint>

using namespace nvcuda;

// ---------------------------------------------------------------------------
// GCNConv: out = X@H0 + A@(X@H1) + A^2@(X@H2)
//   Restructured:  out = Y0 + A@(Y1 + A@Y2),  [Y0|Y1|Y2] = X @ [H0|H1|H2]
// Round 15: SpMM processes 2 edges/iteration — half-warp per edge, uint4
//   gathers, one int4 load for both edges' metadata, shfl_xor(16) reduction.
//   ~25-30% fewer instructions/edge (SpMM measured issue-bound, not BW-bound).
//   GEMM: merged fp16-wmma (X smem tile reused for 3 H's). Build: one-pass
//   padded scatter + overflow list (replayed by spare SpMM warps).
// ---------------------------------------------------------------------------

#define N_NODES_MAX 100000
#define N_EDGES_MAX 3200000
#define FDIM 128
#define SLOTS 128
#define OVF_CAP 8192

__device__ __align__(16) __half g_buf1[(size_t)N_NODES_MAX * FDIM];   // 25.6 MB
__device__ __align__(16) __half g_buf2[(size_t)N_NODES_MAX * FDIM];   // 25.6 MB
__device__ __align__(16) __half g_Hh[3 * FDIM * FDIM];                // H fp16
__device__ int   g_cnt[N_NODES_MAX];
__device__ int   g_ovfCount;
__device__ int3  g_ovf[OVF_CAP];
__device__ __align__(16) int2 g_ecv[(size_t)N_NODES_MAX * SLOTS];     // 102.4 MB

// ---------------------------------------------------------------------------
// H fp32 -> fp16
// ---------------------------------------------------------------------------
__global__ void convH_kernel(const float* __restrict__ H, __half* __restrict__ Hh)
{
    int i = (blockIdx.x * 256 + threadIdx.x) * 4;
    if (i < 3 * FDIM * FDIM) {
        float4 v = *(const float4*)(H + i);
        __half2 h0 = __floats2half2_rn(v.x, v.y);
        __half2 h1 = __floats2half2_rn(v.z, v.w);
        uint2 u;
        u.x = *(unsigned*)&h0;
        u.y = *(unsigned*)&h1;
        *(uint2*)(Hh + i) = u;
    }
}

// ---------------------------------------------------------------------------
// Merged fp16 GEMM (unchanged from R14)
// ---------------------------------------------------------------------------
#define XS_LD2 136
#define HS_LD2 136
#define ST_LD  20
#define GEMM_SMEM (2 * 128 * XS_LD2 * 2)

__global__ __launch_bounds__(256, 2)
void gemm3_merged_kernel(const float* __restrict__ X, const __half* __restrict__ Hh,
                         float* __restrict__ out0, __half* __restrict__ out1,
                         __half* __restrict__ out2, int nN)
{
    extern __shared__ __half sh[];
    __half* Xs = sh;
    __half* Hs = sh + 128 * XS_LD2;
    __shared__ float Stage[8][16 * ST_LD];

    const int tid   = threadIdx.x;
    const int warp  = tid >> 5;
    const int lane  = tid & 31;
    const int warpM = (warp & 1) * 64;
    const int warpN = (warp >> 1) * 32;
    const int rowBase = blockIdx.x * 128;

    for (int g = tid; g < 128 * 16; g += 256) {
        const int row = g >> 4, grp = g & 15;
        const int gr  = rowBase + row;
        uint4 u;
        if (gr < nN) {
            const float* p = X + (size_t)gr * FDIM + grp * 8;
            float4 v0 = *(const float4*)(p);
            float4 v1 = *(const float4*)(p + 4);
            __half2 h0 = __floats2half2_rn(v0.x, v0.y);
            __half2 h1 = __floats2half2_rn(v0.z, v0.w);
            __half2 h2 = __floats2half2_rn(v1.x, v1.y);
            __half2 h3 = __floats2half2_rn(v1.z, v1.w);
            u.x = *(unsigned*)&h0; u.y = *(unsigned*)&h1;
            u.z = *(unsigned*)&h2; u.w = *(unsigned*)&h3;
        } else {
            u = make_uint4(0, 0, 0, 0);
        }
        *(uint4*)&Xs[row * XS_LD2 + grp * 8] = u;
    }
    __syncthreads();

    for (int kSel = 0; kSel < 3; kSel++) {
        const __half* Hk = Hh + (size_t)kSel * FDIM * FDIM;
        for (int g = tid; g < 128 * 16; g += 256) {
            const int r = g >> 4, c = (g & 15) * 8;
            *(uint4*)&Hs[r * HS_LD2 + c] = *(const uint4*)(Hk + (size_t)r * FDIM + c);
        }
        __syncthreads();

        wmma::fragment<wmma::accumulator, 16, 16, 16, float> acc[4][2];
#pragma unroll
        for (int i = 0; i < 4; i++)
#pragma unroll
            for (int j = 0; j < 2; j++) wmma::fill_fragment(acc[i][j], 0.0f);

#pragma unroll
        for (int kk = 0; kk < 8; kk++) {
            wmma::fragment<wmma::matrix_a, 16, 16, 16, __half, wmma::row_major> a[4];
            wmma::fragment<wmma::matrix_b, 16, 16, 16, __half, wmma::row_major> b[2];
#pragma unroll
            for (int i = 0; i < 4; i++)
                wmma::load_matrix_sync(a[i], &Xs[(warpM + i * 16) * XS_LD2 + kk * 16], XS_LD2);
#pragma unroll
            for (int j = 0; j < 2; j++)
                wmma::load_matrix_sync(b[j], &Hs[(kk * 16) * HS_LD2 + warpN + j * 16], HS_LD2);
#pragma unroll
            for (int i = 0; i < 4; i++)
#pragma unroll
                for (int j = 0; j < 2; j++)
                    wmma::mma_sync(acc[i][j], a[i], b[j], acc[i][j]);
        }

        if (kSel == 0) {
            if (rowBase + 128 <= nN) {
#pragma unroll
                for (int i = 0; i < 4; i++)
#pragma unroll
                    for (int j = 0; j < 2; j++) {
                        float* d = out0 + (size_t)(rowBase + warpM + i * 16) * FDIM + warpN + j * 16;
                        wmma::store_matrix_sync(d, acc[i][j], FDIM, wmma::mem_row_major);
                    }
            } else {
#pragma unroll
                for (int i = 0; i < 4; i++)
#pragma unroll
                    for (int j = 0; j < 2; j++) {
                        const int mBase = rowBase + warpM + i * 16;
                        if (mBase >= nN) continue;
                        if (mBase + 16 <= nN) {
                            float* d = out0 + (size_t)mBase * FDIM + warpN + j * 16;
                            wmma::store_matrix_sync(d, acc[i][j], FDIM, wmma::mem_row_major);
                        } else {
                            wmma::store_matrix_sync(&Stage[warp][0], acc[i][j], ST_LD, wmma::mem_row_major);
                            __syncwarp();
                            const int r = lane >> 1, c = (lane & 1) * 8;
                            if (mBase + r < nN) {
                                float* d = out0 + (size_t)(mBase + r) * FDIM + warpN + j * 16 + c;
                                const float* s = &Stage[warp][r * ST_LD + c];
#pragma unroll
                                for (int q = 0; q < 8; q++) d[q] = s[q];
                            }
                            __syncwarp();
                        }
                    }
            }
        } else {
            __half* dstH = (kSel == 1) ? out1 : out2;
#pragma unroll
            for (int i = 0; i < 4; i++)
#pragma unroll
                for (int j = 0; j < 2; j++) {
                    const int mBase = rowBase + warpM + i * 16;
                    if (mBase >= nN) continue;
                    wmma::store_matrix_sync(&Stage[warp][0], acc[i][j], ST_LD, wmma::mem_row_major);
                    __syncwarp();
                    const int r = lane >> 1, c = (lane & 1) * 8;
                    if (mBase + r < nN) {
                        const float* s = &Stage[warp][r * ST_LD + c];
                        __half2 h0 = __floats2half2_rn(s[0], s[1]);
                        __half2 h1 = __floats2half2_rn(s[2], s[3]);
                        __half2 h2 = __floats2half2_rn(s[4], s[5]);
                        __half2 h3 = __floats2half2_rn(s[6], s[7]);
                        uint4 u;
                        u.x = *(unsigned*)&h0; u.y = *(unsigned*)&h1;
                        u.z = *(unsigned*)&h2; u.w = *(unsigned*)&h3;
                        *(uint4*)(dstH + (size_t)(mBase + r) * FDIM + warpN + j * 16 + c) = u;
                    }
                    __syncwarp();
                }
        }
        __syncthreads();
    }
}

// ---------------------------------------------------------------------------
// One-pass padded scatter build
// ---------------------------------------------------------------------------
__global__ void scatter_direct_kernel(const int* __restrict__ rows,
                                      const int* __restrict__ cols,
                                      const float* __restrict__ vals,
                                      int* __restrict__ cnt, int2* __restrict__ ecv,
                                      int* __restrict__ ovfCount, int3* __restrict__ ovf, int nE)
{
    int e = blockIdx.x * 256 + threadIdx.x;
    if (e >= nE) return;
    const int r = rows[e];
    const int c = cols[e];
    const int vb = __float_as_int(vals[e]);
    int pos = atomicAdd(&cnt[r], 1);
    if (pos < SLOTS) {
        ecv[(size_t)r * SLOTS + pos] = make_int2(c, vb);
    } else {
        int o = atomicAdd(ovfCount, 1);
        if (o < OVF_CAP) ovf[o] = make_int3(r, c, vb);
    }
}

// ---------------------------------------------------------------------------
// SpMM, warp per row, 2 edges/iteration:
//   lanes 0-15 handle edge i (uint4 gather of 8 cols each),
//   lanes 16-31 handle edge i+1; one int4 load fetches both edges' (col,val).
//   Cross-half shfl_xor(16) reduction at the end. fp32 accumulation.
// Spare warps (w >= nN) replay the overflow list with atomics (normally 0).
// ---------------------------------------------------------------------------
__device__ __forceinline__ void spmm_row_accum(const int2* __restrict__ e, int deg,
                                               const __half* __restrict__ src,
                                               int lane, float* acc)
{
    const int h     = lane & 15;       // 8-col group within the row
    const int hi    = lane >> 4;       // 0: edge i, 1: edge i+1
    int i = 0;
    for (; i + 1 < deg; i += 2) {
        int4 ee = __ldg((const int4*)(e + i));          // both edges, uniform
        const int   c = hi ? ee.z : ee.x;
        const float v = __int_as_float(hi ? ee.w : ee.y);
        uint4 p = __ldg((const uint4*)(src + (size_t)c * FDIM) + h);
        float2 f0 = __half22float2(*(__half2*)&p.x);
        float2 f1 = __half22float2(*(__half2*)&p.y);
        float2 f2 = __half22float2(*(__half2*)&p.z);
        float2 f3 = __half22float2(*(__half2*)&p.w);
        acc[0] += v * f0.x; acc[1] += v * f0.y;
        acc[2] += v * f1.x; acc[3] += v * f1.y;
        acc[4] += v * f2.x; acc[5] += v * f2.y;
        acc[6] += v * f3.x; acc[7] += v * f3.y;
    }
    if (i < deg) {                                      // odd tail: half 0 only
        int2 cv = __ldg(e + i);
        const float v = hi ? 0.0f : __int_as_float(cv.y);
        uint4 p = __ldg((const uint4*)(src + (size_t)cv.x * FDIM) + h);
        float2 f0 = __half22float2(*(__half2*)&p.x);
        float2 f1 = __half22float2(*(__half2*)&p.y);
        float2 f2 = __half22float2(*(__half2*)&p.z);
        float2 f3 = __half22float2(*(__half2*)&p.w);
        acc[0] += v * f0.x; acc[1] += v * f0.y;
        acc[2] += v * f1.x; acc[3] += v * f1.y;
        acc[4] += v * f2.x; acc[5] += v * f2.y;
        acc[6] += v * f3.x; acc[7] += v * f3.y;
    }
#pragma unroll
    for (int k = 0; k < 8; k++)
        acc[k] += __shfl_xor_sync(0xFFFFFFFFu, acc[k], 16);
}

__global__ __launch_bounds__(256)
void spmm_h2h_kernel(const int* __restrict__ cnt, const int2* __restrict__ ecv,
                     const __half* __restrict__ src, __half* __restrict__ dst,
                     const int* __restrict__ ovfCount, const int3* __restrict__ ovf, int nN)
{
    const int w = (blockIdx.x * 256 + threadIdx.x) >> 5;
    const int lane = threadIdx.x & 31;

    if (w >= nN) {
        const int n = min(*ovfCount, OVF_CAP);
        const int stride = gridDim.x * 8 - nN;
        for (int e = w - nN; e < n; e += stride) {
            int3 t = ovf[e];
            float v = __int_as_float(t.z);
            uint2 p = __ldg((const uint2*)(src + (size_t)t.y * FDIM) + lane);
            float2 f0 = __half22float2(*(__half2*)&p.x);
            float2 f1 = __half22float2(*(__half2*)&p.y);
            __half2* d = (__half2*)(dst + (size_t)t.x * FDIM) + lane * 2;
            atomicAdd(d + 0, __floats2half2_rn(v * f0.x, v * f0.y));
            atomicAdd(d + 1, __floats2half2_rn(v * f1.x, v * f1.y));
        }
        return;
    }

    const int deg = min(__ldg(cnt + w), SLOTS);
    float acc[8] = {0.f, 0.f, 0.f, 0.f, 0.f, 0.f, 0.f, 0.f};
    spmm_row_accum(ecv + (size_t)w * SLOTS, deg, src, lane, acc);

    if (lane < 16) {
        uint4* d = (uint4*)(dst + (size_t)w * FDIM) + lane;
        uint4 cur = *d;
        float2 g0 = __half22float2(*(__half2*)&cur.x);
        float2 g1 = __half22float2(*(__half2*)&cur.y);
        float2 g2 = __half22float2(*(__half2*)&cur.z);
        float2 g3 = __half22float2(*(__half2*)&cur.w);
        __half2 o0 = __floats2half2_rn(g0.x + acc[0], g0.y + acc[1]);
        __half2 o1 = __floats2half2_rn(g1.x + acc[2], g1.y + acc[3]);
        __half2 o2 = __floats2half2_rn(g2.x + acc[4], g2.y + acc[5]);
        __half2 o3 = __floats2half2_rn(g3.x + acc[6], g3.y + acc[7]);
        uint4 o;
        o.x = *(unsigned*)&o0; o.y = *(unsigned*)&o1;
        o.z = *(unsigned*)&o2; o.w = *(unsigned*)&o3;
        *d = o;
    }
}

__global__ __launch_bounds__(256)
void spmm_h2f_kernel(const int* __restrict__ cnt, const int2* __restrict__ ecv,
                     const __half* __restrict__ src, float* __restrict__ dst,
                     const int* __restrict__ ovfCount, const int3* __restrict__ ovf, int nN)
{
    const int w = (blockIdx.x * 256 + threadIdx.x) >> 5;
    const int lane = threadIdx.x & 31;

    if (w >= nN) {
        const int n = min(*ovfCount, OVF_CAP);
        const int stride = gridDim.x * 8 - nN;
        for (int e = w - nN; e < n; e += stride) {
            int3 t = ovf[e];
            float v = __int_as_float(t.z);
            uint2 p = __ldg((const uint2*)(src + (size_t)t.y * FDIM) + lane);
            float2 f0 = __half22float2(*(__half2*)&p.x);
            float2 f1 = __half22float2(*(__half2*)&p.y);
            float* d = dst + (size_t)t.x * FDIM + lane * 4;
            atomicAdd(d + 0, v * f0.x);
            atomicAdd(d + 1, v * f0.y);
            atomicAdd(d + 2, v * f1.x);
            atomicAdd(d + 3, v * f1.y);
        }
        return;
    }

    const int deg = min(__ldg(cnt + w), SLOTS);
    float acc[8] = {0.f, 0.f, 0.f, 0.f, 0.f, 0.f, 0.f, 0.f};
    spmm_row_accum(ecv + (size_t)w * SLOTS, deg, src, lane, acc);

    if (lane < 16) {
        float4* d = (float4*)(dst + (size_t)w * FDIM) + lane * 2;
        float4 c0 = d[0], c1 = d[1];
        c0.x += acc[0]; c0.y += acc[1]; c0.z += acc[2]; c0.w += acc[3];
        c1.x += acc[4]; c1.y += acc[5]; c1.z += acc[6]; c1.w += acc[7];
        d[0] = c0; d[1] = c1;
    }
}

// ---------------------------------------------------------------------------
extern "C" void kernel_launch(void* const* d_in, const int* in_sizes, int n_in,
                              void* d_out, int out_size)
{
    const int*   rows = (const int*)d_in[0];
    const int*   cols = (const int*)d_in[1];
    const float* vals = (const float*)d_in[2];
    const float* x    = (const float*)d_in[3];
    const float* H    = (const float*)d_in[4];
    float*       out  = (float*)d_out;

    const int nE = in_sizes[0];
    const int nN = in_sizes[3] / FDIM;

    __half *buf1, *buf2, *Hh;
    int *cnt, *ovfCount;
    int3 *ovf;
    int2 *ecv;
    cudaGetSymbolAddress((void**)&buf1, g_buf1);
    cudaGetSymbolAddress((void**)&buf2, g_buf2);
    cudaGetSymbolAddress((void**)&Hh, g_Hh);
    cudaGetSymbolAddress((void**)&cnt, g_cnt);
    cudaGetSymbolAddress((void**)&ovfCount, g_ovfCount);
    cudaGetSymbolAddress((void**)&ovf, g_ovf);
    cudaGetSymbolAddress((void**)&ecv, g_ecv);

    static cudaStream_t sGemm = nullptr;
    static cudaEvent_t  evFork = nullptr, evGemm = nullptr;
    if (sGemm == nullptr) {
        cudaStreamCreateWithFlags(&sGemm, cudaStreamNonBlocking);
        cudaEventCreateWithFlags(&evFork, cudaEventDisableTiming);
        cudaEventCreateWithFlags(&evGemm, cudaEventDisableTiming);
        cudaFuncSetAttribute(gemm3_merged_kernel,
                             cudaFuncAttributeMaxDynamicSharedMemorySize, GEMM_SMEM);
    }

    const int eBlocks = (nE + 255) / 256;
    const int mTiles  = (nN + 127) / 128;

    // ---- fork: H conversion + merged GEMM on side stream ----
    cudaEventRecord(evFork, 0);
    cudaStreamWaitEvent(sGemm, evFork, 0);
    convH_kernel<<<48, 256, 0, sGemm>>>(H, Hh);
    gemm3_merged_kernel<<<mTiles, 256, GEMM_SMEM, sGemm>>>(x, Hh, out, buf1, buf2, nN);
    cudaEventRecord(evGemm, sGemm);

    // ---- one-pass padded scatter on main stream (overlaps GEMM) ----
    cudaMemsetAsync(cnt, 0, (size_t)nN * sizeof(int), 0);
    cudaMemsetAsync(ovfCount, 0, sizeof(int), 0);
    scatter_direct_kernel<<<eBlocks, 256>>>(rows, cols, vals, cnt, ecv, ovfCount, ovf, nE);

    // ---- join, then two SpMM passes (spare warps handle overflow) ----
    cudaStreamWaitEvent(0, evGemm, 0);
    const int spmmBlocks = (int)(((long long)nN * 32 + 255) / 256) + 1;
    spmm_h2h_kernel<<<spmmBlocks, 256>>>(cnt, ecv, buf2, buf1, ovfCount, ovf, nN);
    spmm_h2f_kernel<<<spmmBlocks, 256>>>(cnt, ecv, buf1, out, ovfCount, ovf, nN);
}

// round 17
// speedup vs baseline: 1.1166x; 1.1166x over previous
#include <cuda_runtime.h>
#include <cuda_fp16.h>
#include <mma.h>
#include <cstdint>

using namespace nvcuda;

// ---------------------------------------------------------------------------
// GCNConv: out = X@H0 + A@(X@H1) + A^2@(X@H2)
//   Restructured:  out = Y0 + A@(Y1 + A@Y2),  [Y0|Y1|Y2] = X @ [H0|H1|H2]
// Round 17 = R14 (270us best) + SpMM software pipeline: 8 edges per
//   iteration, metadata via 4 uniform int4 loads, 8 independent gathers in
//   flight (MLP 4 -> 8). Same per-lane accumulation order as R14 (bit-
//   identical output). GEMM: merged fp16-wmma. Build: padded scatter.
// ---------------------------------------------------------------------------

#define N_NODES_MAX 100000
#define N_EDGES_MAX 3200000
#define FDIM 128
#define SLOTS 128
#define OVF_CAP 8192

__device__ __align__(16) __half g_buf1[(size_t)N_NODES_MAX * FDIM];   // 25.6 MB
__device__ __align__(16) __half g_buf2[(size_t)N_NODES_MAX * FDIM];   // 25.6 MB
__device__ __align__(16) __half g_Hh[3 * FDIM * FDIM];                // H fp16
__device__ int   g_cnt[N_NODES_MAX];
__device__ int   g_ovfCount;
__device__ int3  g_ovf[OVF_CAP];
__device__ __align__(16) int2 g_ecv[(size_t)N_NODES_MAX * SLOTS];     // 102.4 MB

// ---------------------------------------------------------------------------
// H fp32 -> fp16
// ---------------------------------------------------------------------------
__global__ void convH_kernel(const float* __restrict__ H, __half* __restrict__ Hh)
{
    int i = (blockIdx.x * 256 + threadIdx.x) * 4;
    if (i < 3 * FDIM * FDIM) {
        float4 v = *(const float4*)(H + i);
        __half2 h0 = __floats2half2_rn(v.x, v.y);
        __half2 h1 = __floats2half2_rn(v.z, v.w);
        uint2 u;
        u.x = *(unsigned*)&h0;
        u.y = *(unsigned*)&h1;
        *(uint2*)(Hh + i) = u;
    }
}

// ---------------------------------------------------------------------------
// Merged fp16 GEMM (unchanged from R14)
// ---------------------------------------------------------------------------
#define XS_LD2 136
#define HS_LD2 136
#define ST_LD  20
#define GEMM_SMEM (2 * 128 * XS_LD2 * 2)

__global__ __launch_bounds__(256, 2)
void gemm3_merged_kernel(const float* __restrict__ X, const __half* __restrict__ Hh,
                         float* __restrict__ out0, __half* __restrict__ out1,
                         __half* __restrict__ out2, int nN)
{
    extern __shared__ __half sh[];
    __half* Xs = sh;
    __half* Hs = sh + 128 * XS_LD2;
    __shared__ float Stage[8][16 * ST_LD];

    const int tid   = threadIdx.x;
    const int warp  = tid >> 5;
    const int lane  = tid & 31;
    const int warpM = (warp & 1) * 64;
    const int warpN = (warp >> 1) * 32;
    const int rowBase = blockIdx.x * 128;

    for (int g = tid; g < 128 * 16; g += 256) {
        const int row = g >> 4, grp = g & 15;
        const int gr  = rowBase + row;
        uint4 u;
        if (gr < nN) {
            const float* p = X + (size_t)gr * FDIM + grp * 8;
            float4 v0 = *(const float4*)(p);
            float4 v1 = *(const float4*)(p + 4);
            __half2 h0 = __floats2half2_rn(v0.x, v0.y);
            __half2 h1 = __floats2half2_rn(v0.z, v0.w);
            __half2 h2 = __floats2half2_rn(v1.x, v1.y);
            __half2 h3 = __floats2half2_rn(v1.z, v1.w);
            u.x = *(unsigned*)&h0; u.y = *(unsigned*)&h1;
            u.z = *(unsigned*)&h2; u.w = *(unsigned*)&h3;
        } else {
            u = make_uint4(0, 0, 0, 0);
        }
        *(uint4*)&Xs[row * XS_LD2 + grp * 8] = u;
    }
    __syncthreads();

    for (int kSel = 0; kSel < 3; kSel++) {
        const __half* Hk = Hh + (size_t)kSel * FDIM * FDIM;
        for (int g = tid; g < 128 * 16; g += 256) {
            const int r = g >> 4, c = (g & 15) * 8;
            *(uint4*)&Hs[r * HS_LD2 + c] = *(const uint4*)(Hk + (size_t)r * FDIM + c);
        }
        __syncthreads();

        wmma::fragment<wmma::accumulator, 16, 16, 16, float> acc[4][2];
#pragma unroll
        for (int i = 0; i < 4; i++)
#pragma unroll
            for (int j = 0; j < 2; j++) wmma::fill_fragment(acc[i][j], 0.0f);

#pragma unroll
        for (int kk = 0; kk < 8; kk++) {
            wmma::fragment<wmma::matrix_a, 16, 16, 16, __half, wmma::row_major> a[4];
            wmma::fragment<wmma::matrix_b, 16, 16, 16, __half, wmma::row_major> b[2];
#pragma unroll
            for (int i = 0; i < 4; i++)
                wmma::load_matrix_sync(a[i], &Xs[(warpM + i * 16) * XS_LD2 + kk * 16], XS_LD2);
#pragma unroll
            for (int j = 0; j < 2; j++)
                wmma::load_matrix_sync(b[j], &Hs[(kk * 16) * HS_LD2 + warpN + j * 16], HS_LD2);
#pragma unroll
            for (int i = 0; i < 4; i++)
#pragma unroll
                for (int j = 0; j < 2; j++)
                    wmma::mma_sync(acc[i][j], a[i], b[j], acc[i][j]);
        }

        if (kSel == 0) {
            if (rowBase + 128 <= nN) {
#pragma unroll
                for (int i = 0; i < 4; i++)
#pragma unroll
                    for (int j = 0; j < 2; j++) {
                        float* d = out0 + (size_t)(rowBase + warpM + i * 16) * FDIM + warpN + j * 16;
                        wmma::store_matrix_sync(d, acc[i][j], FDIM, wmma::mem_row_major);
                    }
            } else {
#pragma unroll
                for (int i = 0; i < 4; i++)
#pragma unroll
                    for (int j = 0; j < 2; j++) {
                        const int mBase = rowBase + warpM + i * 16;
                        if (mBase >= nN) continue;
                        if (mBase + 16 <= nN) {
                            float* d = out0 + (size_t)mBase * FDIM + warpN + j * 16;
                            wmma::store_matrix_sync(d, acc[i][j], FDIM, wmma::mem_row_major);
                        } else {
                            wmma::store_matrix_sync(&Stage[warp][0], acc[i][j], ST_LD, wmma::mem_row_major);
                            __syncwarp();
                            const int r = lane >> 1, c = (lane & 1) * 8;
                            if (mBase + r < nN) {
                                float* d = out0 + (size_t)(mBase + r) * FDIM + warpN + j * 16 + c;
                                const float* s = &Stage[warp][r * ST_LD + c];
#pragma unroll
                                for (int q = 0; q < 8; q++) d[q] = s[q];
                            }
                            __syncwarp();
                        }
                    }
            }
        } else {
            __half* dstH = (kSel == 1) ? out1 : out2;
#pragma unroll
            for (int i = 0; i < 4; i++)
#pragma unroll
                for (int j = 0; j < 2; j++) {
                    const int mBase = rowBase + warpM + i * 16;
                    if (mBase >= nN) continue;
                    wmma::store_matrix_sync(&Stage[warp][0], acc[i][j], ST_LD, wmma::mem_row_major);
                    __syncwarp();
                    const int r = lane >> 1, c = (lane & 1) * 8;
                    if (mBase + r < nN) {
                        const float* s = &Stage[warp][r * ST_LD + c];
                        __half2 h0 = __floats2half2_rn(s[0], s[1]);
                        __half2 h1 = __floats2half2_rn(s[2], s[3]);
                        __half2 h2 = __floats2half2_rn(s[4], s[5]);
                        __half2 h3 = __floats2half2_rn(s[6], s[7]);
                        uint4 u;
                        u.x = *(unsigned*)&h0; u.y = *(unsigned*)&h1;
                        u.z = *(unsigned*)&h2; u.w = *(unsigned*)&h3;
                        *(uint4*)(dstH + (size_t)(mBase + r) * FDIM + warpN + j * 16 + c) = u;
                    }
                    __syncwarp();
                }
        }
        __syncthreads();
    }
}

// ---------------------------------------------------------------------------
// One-pass padded scatter build
// ---------------------------------------------------------------------------
__global__ void scatter_direct_kernel(const int* __restrict__ rows,
                                      const int* __restrict__ cols,
                                      const float* __restrict__ vals,
                                      int* __restrict__ cnt, int2* __restrict__ ecv,
                                      int* __restrict__ ovfCount, int3* __restrict__ ovf, int nE)
{
    int e = blockIdx.x * 256 + threadIdx.x;
    if (e >= nE) return;
    const int r = rows[e];
    const int c = cols[e];
    const int vb = __float_as_int(vals[e]);
    int pos = atomicAdd(&cnt[r], 1);
    if (pos < SLOTS) {
        ecv[(size_t)r * SLOTS + pos] = make_int2(c, vb);
    } else {
        int o = atomicAdd(ovfCount, 1);
        if (o < OVF_CAP) ovf[o] = make_int3(r, c, vb);
    }
}

// ---------------------------------------------------------------------------
// SpMM row accumulation: 8 edges per iteration, 8 gathers in flight (MLP=8).
// Same per-lane edge order as scalar loop -> bit-identical accumulation.
// ---------------------------------------------------------------------------
#define EDGE_ACC(P, VB)                                       \
    do {                                                      \
        const float v_ = __int_as_float(VB);                  \
        float2 f0_ = __half22float2(*(__half2*)&(P).x);       \
        float2 f1_ = __half22float2(*(__half2*)&(P).y);       \
        acc.x += v_ * f0_.x; acc.y += v_ * f0_.y;             \
        acc.z += v_ * f1_.x; acc.w += v_ * f1_.y;             \
    } while (0)

__device__ __forceinline__ float4 spmm_row_accum(const int2* __restrict__ e, int deg,
                                                 const __half* __restrict__ src, int lane)
{
    float4 acc = make_float4(0.f, 0.f, 0.f, 0.f);
    int i = 0;
    for (; i + 8 <= deg; i += 8) {
        const int4* m = (const int4*)(e + i);        // 16B-aligned (i % 8 == 0)
        int4 m0 = __ldg(m + 0);
        int4 m1 = __ldg(m + 1);
        int4 m2 = __ldg(m + 2);
        int4 m3 = __ldg(m + 3);
        uint2 p0 = __ldg((const uint2*)(src + (size_t)m0.x * FDIM) + lane);
        uint2 p1 = __ldg((const uint2*)(src + (size_t)m0.z * FDIM) + lane);
        uint2 p2 = __ldg((const uint2*)(src + (size_t)m1.x * FDIM) + lane);
        uint2 p3 = __ldg((const uint2*)(src + (size_t)m1.z * FDIM) + lane);
        uint2 p4 = __ldg((const uint2*)(src + (size_t)m2.x * FDIM) + lane);
        uint2 p5 = __ldg((const uint2*)(src + (size_t)m2.z * FDIM) + lane);
        uint2 p6 = __ldg((const uint2*)(src + (size_t)m3.x * FDIM) + lane);
        uint2 p7 = __ldg((const uint2*)(src + (size_t)m3.z * FDIM) + lane);
        EDGE_ACC(p0, m0.y); EDGE_ACC(p1, m0.w);
        EDGE_ACC(p2, m1.y); EDGE_ACC(p3, m1.w);
        EDGE_ACC(p4, m2.y); EDGE_ACC(p5, m2.w);
        EDGE_ACC(p6, m3.y); EDGE_ACC(p7, m3.w);
    }
    for (; i < deg; i++) {
        int2 cv = __ldg(e + i);
        uint2 p = __ldg((const uint2*)(src + (size_t)cv.x * FDIM) + lane);
        EDGE_ACC(p, cv.y);
    }
    return acc;
}

// ---------------------------------------------------------------------------
// SpMM kernels (warp per row). Spare warps replay the overflow list.
// ---------------------------------------------------------------------------
__global__ __launch_bounds__(256)
void spmm_h2h_kernel(const int* __restrict__ cnt, const int2* __restrict__ ecv,
                     const __half* __restrict__ src, __half* __restrict__ dst,
                     const int* __restrict__ ovfCount, const int3* __restrict__ ovf, int nN)
{
    const int w = (blockIdx.x * 256 + threadIdx.x) >> 5;
    const int lane = threadIdx.x & 31;

    if (w >= nN) {
        const int n = min(*ovfCount, OVF_CAP);
        const int stride = gridDim.x * 8 - nN;
        for (int e = w - nN; e < n; e += stride) {
            int3 t = ovf[e];
            float v = __int_as_float(t.z);
            uint2 p = __ldg((const uint2*)(src + (size_t)t.y * FDIM) + lane);
            float2 f0 = __half22float2(*(__half2*)&p.x);
            float2 f1 = __half22float2(*(__half2*)&p.y);
            __half2* d = (__half2*)(dst + (size_t)t.x * FDIM) + lane * 2;
            atomicAdd(d + 0, __floats2half2_rn(v * f0.x, v * f0.y));
            atomicAdd(d + 1, __floats2half2_rn(v * f1.x, v * f1.y));
        }
        return;
    }

    const int deg = min(__ldg(cnt + w), SLOTS);
    float4 acc = spmm_row_accum(ecv + (size_t)w * SLOTS, deg, src, lane);

    uint2* d  = (uint2*)(dst + (size_t)w * FDIM) + lane;
    uint2 cur = *d;
    float2 g0 = __half22float2(*(__half2*)&cur.x);
    float2 g1 = __half22float2(*(__half2*)&cur.y);
    g0.x += acc.x; g0.y += acc.y; g1.x += acc.z; g1.y += acc.w;
    __half2 o0 = __floats2half2_rn(g0.x, g0.y);
    __half2 o1 = __floats2half2_rn(g1.x, g1.y);
    uint2 o; o.x = *(unsigned*)&o0; o.y = *(unsigned*)&o1;
    *d = o;
}

__global__ __launch_bounds__(256)
void spmm_h2f_kernel(const int* __restrict__ cnt, const int2* __restrict__ ecv,
                     const __half* __restrict__ src, float* __restrict__ dst,
                     const int* __restrict__ ovfCount, const int3* __restrict__ ovf, int nN)
{
    const int w = (blockIdx.x * 256 + threadIdx.x) >> 5;
    const int lane = threadIdx.x & 31;

    if (w >= nN) {
        const int n = min(*ovfCount, OVF_CAP);
        const int stride = gridDim.x * 8 - nN;
        for (int e = w - nN; e < n; e += stride) {
            int3 t = ovf[e];
            float v = __int_as_float(t.z);
            uint2 p = __ldg((const uint2*)(src + (size_t)t.y * FDIM) + lane);
            float2 f0 = __half22float2(*(__half2*)&p.x);
            float2 f1 = __half22float2(*(__half2*)&p.y);
            float* d = dst + (size_t)t.x * FDIM + lane * 4;
            atomicAdd(d + 0, v * f0.x);
            atomicAdd(d + 1, v * f0.y);
            atomicAdd(d + 2, v * f1.x);
            atomicAdd(d + 3, v * f1.y);
        }
        return;
    }

    const int deg = min(__ldg(cnt + w), SLOTS);
    float4 acc = spmm_row_accum(ecv + (size_t)w * SLOTS, deg, src, lane);

    float4* d  = (float4*)(dst + (size_t)w * FDIM) + lane;
    float4 cur = *d;
    cur.x += acc.x; cur.y += acc.y; cur.z += acc.z; cur.w += acc.w;
    *d = cur;
}

// ---------------------------------------------------------------------------
extern "C" void kernel_launch(void* const* d_in, const int* in_sizes, int n_in,
                              void* d_out, int out_size)
{
    const int*   rows = (const int*)d_in[0];
    const int*   cols = (const int*)d_in[1];
    const float* vals = (const float*)d_in[2];
    const float* x    = (const float*)d_in[3];
    const float* H    = (const float*)d_in[4];
    float*       out  = (float*)d_out;

    const int nE = in_sizes[0];
    const int nN = in_sizes[3] / FDIM;

    __half *buf1, *buf2, *Hh;
    int *cnt, *ovfCount;
    int3 *ovf;
    int2 *ecv;
    cudaGetSymbolAddress((void**)&buf1, g_buf1);
    cudaGetSymbolAddress((void**)&buf2, g_buf2);
    cudaGetSymbolAddress((void**)&Hh, g_Hh);
    cudaGetSymbolAddress((void**)&cnt, g_cnt);
    cudaGetSymbolAddress((void**)&ovfCount, g_ovfCount);
    cudaGetSymbolAddress((void**)&ovf, g_ovf);
    cudaGetSymbolAddress((void**)&ecv, g_ecv);

    static cudaStream_t sGemm = nullptr;
    static cudaEvent_t  evFork = nullptr, evGemm = nullptr;
    if (sGemm == nullptr) {
        cudaStreamCreateWithFlags(&sGemm, cudaStreamNonBlocking);
        cudaEventCreateWithFlags(&evFork, cudaEventDisableTiming);
        cudaEventCreateWithFlags(&evGemm, cudaEventDisableTiming);
        cudaFuncSetAttribute(gemm3_merged_kernel,
                             cudaFuncAttributeMaxDynamicSharedMemorySize, GEMM_SMEM);
    }

    const int eBlocks = (nE + 255) / 256;
    const int mTiles  = (nN + 127) / 128;

    // ---- fork: H conversion + merged GEMM on side stream ----
    cudaEventRecord(evFork, 0);
    cudaStreamWaitEvent(sGemm, evFork, 0);
    convH_kernel<<<48, 256, 0, sGemm>>>(H, Hh);
    gemm3_merged_kernel<<<mTiles, 256, GEMM_SMEM, sGemm>>>(x, Hh, out, buf1, buf2, nN);
    cudaEventRecord(evGemm, sGemm);

    // ---- one-pass padded scatter on main stream (overlaps GEMM) ----
    cudaMemsetAsync(cnt, 0, (size_t)nN * sizeof(int), 0);
    cudaMemsetAsync(ovfCount, 0, sizeof(int), 0);
    scatter_direct_kernel<<<eBlocks, 256>>>(rows, cols, vals, cnt, ecv, ovfCount, ovf, nE);

    // ---- join, then two SpMM passes (spare warps handle overflow) ----
    cudaStreamWaitEvent(0, evGemm, 0);
    const int spmmBlocks = (int)(((long long)nN * 32 + 255) / 256) + 1;
    spmm_h2h_kernel<<<spmmBlocks, 256>>>(cnt, ecv, buf2, buf1, ovfCount, ovf, nN);
    spmm_h2f_kernel<<<spmmBlocks, 256>>>(cnt, ecv, buf1, out, ovfCount, ovf, nN);
}